// round 15
// baseline (speedup 1.0000x reference)
#include <cuda_runtime.h>
#include <cuda_fp16.h>
#include <math.h>

#define NN 100000
#define NE 3200000
#define FIN 32
#define HD 64
#define NL 4
#define NA 6158
#define NG 64
#define WPAD 68

// dynamic smem layout for k_layer (floats):
//  Wls [0,4352) | Wrs [4352,8704) | bls [8704,8768) | stA [8768,17472) | stH [17472,26176)
#define OFF_WLS 0
#define OFF_WRS 4352
#define OFF_BLS 8704
#define OFF_STA 8768
#define OFF_STH 17472
#define LAYER_SMEM_FLOATS 26176
#define LAYER_SMEM_BYTES (LAYER_SMEM_FLOATS * 4)

// ---------------- scratch (device globals; no allocation allowed) -------------
__device__ int   d_flag;
__device__ int   d_batch32[NN];
__device__ int   d_deg[NN];
__device__ int   d_rowptr[NN + 1];
__device__ int   d_cursor[NN];
__device__ int   d_csr[NE];
__device__ float d_invdeg[NN];
__device__ float d_h0[NN * HD];
__device__ float d_h1[NN * HD];
__device__ float d_scr[NN * HD];       // dummy-layer sink (never read)
__device__ __half2 d_hh[NN * 32];
__device__ __half2 d_agg16[NN * 32];
__device__ float d_gsum[NG * HD];
__device__ int   d_gcnt[NG];
__device__ int   d_part[256];

// ---------------- f32x2 packed-FMA helpers -------------------------------------
__device__ __forceinline__ unsigned long long pack2(float x) {
    unsigned long long r;
    asm("mov.b64 %0, {%1, %1};" : "=l"(r) : "f"(x));
    return r;
}
__device__ __forceinline__ void ffma2(unsigned long long& d,
                                      unsigned long long a,
                                      unsigned long long b) {
    asm("fma.rn.f32x2 %0, %1, %2, %0;" : "+l"(d) : "l"(a), "l"(b));
}
__device__ __forceinline__ void unpack2(unsigned long long v, float& lo, float& hi) {
    asm("mov.b64 {%0, %1}, %2;" : "=f"(lo), "=f"(hi) : "l"(v));
}

// ---------------- degree count straight from edge dst half ----------------------
__global__ void k_degree(const void* edge) {
    __shared__ int sflag;
    if (threadIdx.x < 32) {
        const unsigned int* w = (const unsigned int*)edge;
        unsigned int m0 = __ballot_sync(0xffffffffu, w[2 * threadIdx.x + 1] == 0u);
        unsigned int m1 = __ballot_sync(0xffffffffu, w[2 * (threadIdx.x + 32) + 1] == 0u);
        if (threadIdx.x == 0) {
            int f = (__popc(m0) + __popc(m1) >= 60) ? 1 : 0;
            sflag = f;
            if (blockIdx.x == 0) d_flag = f;
        }
    }
    __syncthreads();
    int e = blockIdx.x * blockDim.x + threadIdx.x;
    if (e >= NE) return;
    int dd;
    if (sflag) dd = (int)((const long long*)edge)[NE + e];
    else       dd = ((const int*)edge)[NE + e];
    atomicAdd(&d_deg[dd], 1);
}

// ---------------- CSR build (scan over degrees) --------------------------------
__global__ void k_scan_a() {
    __shared__ int ts[256];
    int b = blockIdx.x, t = threadIdx.x;
    int base = b * 1024 + t * 4;
    int v[4];
    int s = 0;
#pragma unroll
    for (int j = 0; j < 4; j++) {
        int idx = base + j;
        v[j] = (idx < NN) ? d_deg[idx] : 0;
        s += v[j];
    }
    ts[t] = s;
    __syncthreads();
    for (int off = 1; off < 256; off <<= 1) {
        int x = (t >= off) ? ts[t - off] : 0;
        __syncthreads();
        ts[t] += x;
        __syncthreads();
    }
    int run = ts[t] - s;
#pragma unroll
    for (int j = 0; j < 4; j++) {
        int idx = base + j;
        if (idx < NN) d_rowptr[idx] = run;
        run += v[j];
    }
    if (t == 255) d_part[b] = ts[255];
}

// scan finalize + invdeg + batch conversion
__global__ void k_scan_c(const void* batch) {
    __shared__ int ps[128];
    int t = threadIdx.x;
    int orig = (t < 98) ? d_part[t] : 0;
    if (t < 128) ps[t] = orig;
    __syncthreads();
    for (int off = 1; off < 128; off <<= 1) {
        int x = (t >= off && t < 128) ? ps[t - off] : 0;
        __syncthreads();
        if (t < 128) ps[t] += x;
        __syncthreads();
    }
    if (t < 128) ps[t] -= orig;   // exclusive
    __syncthreads();

    int i = blockIdx.x * blockDim.x + t;
    if (i == 0) d_rowptr[NN] = NE;
    if (i >= NN) return;
    int r = d_rowptr[i] + ps[i >> 10];
    d_rowptr[i] = r;
    d_cursor[i] = r;
    d_invdeg[i] = 1.0f / fmaxf((float)d_deg[i], 1.0f);
    int b;
    if (d_flag) b = (int)((const long long*)batch)[i];
    else        b = ((const int*)batch)[i];
    d_batch32[i] = b;
}

// scatter edges into CSR, converting src/dst inline; zeroes gsum/gcnt
__global__ void k_scatter(const void* edge) {
    int e = blockIdx.x * blockDim.x + threadIdx.x;
    if (e < NG * HD) d_gsum[e] = 0.f;
    if (e < NG) d_gcnt[e] = 0;
    if (e >= NE) return;
    int ss, dd;
    if (d_flag) {
        ss = (int)((const long long*)edge)[e];
        dd = (int)((const long long*)edge)[NE + e];
    } else {
        ss = ((const int*)edge)[e];
        dd = ((const int*)edge)[NE + e];
    }
    int pos = atomicAdd(&d_cursor[dd], 1);
    d_csr[pos] = ss;
}

// ---------------- encoder: h0 = relu(x @ W_enc^T + b_enc) ----------------------
__global__ void k_encoder(const float* __restrict__ x,
                          const float* __restrict__ Wenc,
                          const float* __restrict__ benc) {
    __shared__ float Ws[FIN * HD];
    __shared__ float bs[HD];
    int t = threadIdx.x;
    int gid = blockIdx.x * blockDim.x + t;
    for (int i = t; i < HD * FIN; i += blockDim.x) {
        int j = i / FIN, k = i % FIN;
        Ws[k * HD + j] = Wenc[i];
    }
    if (t < HD) bs[t] = benc[t];
    __syncthreads();
    if (gid >= NN * 32) return;
    int n = gid >> 5, j2 = gid & 31;
    int j = 2 * j2;
    const float* xr = x + n * FIN;
    float a0 = bs[j], a1 = bs[j + 1];
#pragma unroll
    for (int k = 0; k < FIN; k += 4) {
        float4 xv = *(const float4*)(xr + k);
        float2 w0 = *(const float2*)(&Ws[k * HD + j]);
        float2 w1 = *(const float2*)(&Ws[(k + 1) * HD + j]);
        float2 w2 = *(const float2*)(&Ws[(k + 2) * HD + j]);
        float2 w3 = *(const float2*)(&Ws[(k + 3) * HD + j]);
        a0 += xv.x * w0.x + xv.y * w1.x + xv.z * w2.x + xv.w * w3.x;
        a1 += xv.x * w0.y + xv.y * w1.y + xv.z * w2.y + xv.w * w3.y;
    }
    a0 = fmaxf(a0, 0.f);
    a1 = fmaxf(a1, 0.f);
    ((float2*)d_h0)[gid] = make_float2(a0, a1);
    d_hh[gid] = __floats2half2_rn(a0, a1);
}

// ---------------- aggregation -> fp16 -------------------------------------------
__global__ void k_aggregate() {
    int w = (blockIdx.x * blockDim.x + threadIdx.x) >> 5;
    if (w >= NN) return;
    int lane = threadIdx.x & 31;
    int beg = d_rowptr[w], end = d_rowptr[w + 1];
    const __half2* __restrict__ hp = d_hh;
    float ax0 = 0.f, ay0 = 0.f, ax1 = 0.f, ay1 = 0.f;
    int i = beg;
    for (; i + 8 <= end; i += 8) {
        int s0 = d_csr[i + 0], s1 = d_csr[i + 1], s2 = d_csr[i + 2], s3 = d_csr[i + 3];
        int s4 = d_csr[i + 4], s5 = d_csr[i + 5], s6 = d_csr[i + 6], s7 = d_csr[i + 7];
        float2 v0 = __half22float2(hp[s0 * 32 + lane]);
        float2 v1 = __half22float2(hp[s1 * 32 + lane]);
        float2 v2 = __half22float2(hp[s2 * 32 + lane]);
        float2 v3 = __half22float2(hp[s3 * 32 + lane]);
        float2 v4 = __half22float2(hp[s4 * 32 + lane]);
        float2 v5 = __half22float2(hp[s5 * 32 + lane]);
        float2 v6 = __half22float2(hp[s6 * 32 + lane]);
        float2 v7 = __half22float2(hp[s7 * 32 + lane]);
        ax0 += v0.x + v1.x + v2.x + v3.x;
        ay0 += v0.y + v1.y + v2.y + v3.y;
        ax1 += v4.x + v5.x + v6.x + v7.x;
        ay1 += v4.y + v5.y + v6.y + v7.y;
    }
    for (; i < end; i++) {
        float2 v = __half22float2(hp[d_csr[i] * 32 + lane]);
        ax0 += v.x; ay0 += v.y;
    }
    float id = d_invdeg[w];
    d_agg16[w * 32 + lane] = __floats2half2_rn((ax0 + ax1) * id, (ay0 + ay1) * id);
}

// ---------------- layer v6 (+ mode 2 = dummy/profiling: h0 -> d_scr) ------------
__global__ void __launch_bounds__(256, 2)
k_layer(int mode, int write_hh,
        const float* __restrict__ Wl, const float* __restrict__ bl,
        const float* __restrict__ Wr) {
    const float* h    = (mode == 1) ? d_h1 : d_h0;
    float*       hout = (mode == 0) ? d_h1 : ((mode == 1) ? d_h0 : d_scr);
    extern __shared__ float S[];
    float* Wls = S + OFF_WLS;
    float* Wrs = S + OFF_WRS;
    float* bls = S + OFF_BLS;
    float* stA = S + OFF_STA;
    float* stH = S + OFF_STH;
    int t = threadIdx.x;
    int base = blockIdx.x * 128;

    for (int i = t; i < HD * HD; i += 256) {
        int j = i >> 6, k = i & 63;
        Wls[k * WPAD + j] = Wl[i];
        Wrs[k * WPAD + j] = Wr[i];
    }
    if (t < HD) bls[t] = bl[t];

    for (int i = t; i < 2048; i += 256) {
        int row = i >> 4, f = i & 15;
        int gn = base + row;
        if (gn < NN)
            *(float4*)&stH[row * WPAD + f * 4] = ((const float4*)(h + gn * 64))[f];
    }
    for (int i = t; i < 1024; i += 256) {
        int row = i >> 3, f = i & 7;
        int gn = base + row;
        if (gn < NN) {
            uint4 q = ((const uint4*)(d_agg16 + gn * 32))[f];
            const __half2* hq = (const __half2*)&q;
            float2 f0 = __half22float2(hq[0]);
            float2 f1 = __half22float2(hq[1]);
            float2 f2 = __half22float2(hq[2]);
            float2 f3 = __half22float2(hq[3]);
            float* dst = &stA[row * WPAD + f * 8];
            *(float4*)(dst)     = make_float4(f0.x, f0.y, f1.x, f1.y);
            *(float4*)(dst + 4) = make_float4(f2.x, f2.y, f3.x, f3.y);
        }
    }
    __syncthreads();

    int p  = t & 63;
    int jq = t >> 6;

    unsigned long long accA[8], accB[8];
    {
        const unsigned long long* bp2 = (const unsigned long long*)(bls + jq * 16);
#pragma unroll
        for (int q = 0; q < 8; q++) { accA[q] = bp2[q]; accB[q] = bp2[q]; }
    }

#pragma unroll 2
    for (int k4 = 0; k4 < 16; k4++) {
        float4 aA = *(const float4*)&stA[p * WPAD + k4 * 4];
        float4 hA = *(const float4*)&stH[p * WPAD + k4 * 4];
        float4 aB = *(const float4*)&stA[(p + 64) * WPAD + k4 * 4];
        float4 hB = *(const float4*)&stH[(p + 64) * WPAD + k4 * 4];
        float aAv[4] = {aA.x, aA.y, aA.z, aA.w};
        float hAv[4] = {hA.x, hA.y, hA.z, hA.w};
        float aBv[4] = {aB.x, aB.y, aB.z, aB.w};
        float hBv[4] = {hB.x, hB.y, hB.z, hB.w};
#pragma unroll
        for (int kk = 0; kk < 4; kk++) {
            int k = k4 * 4 + kk;
            const ulonglong2* __restrict__ wl =
                (const ulonglong2*)(Wls + k * WPAD + jq * 16);
            const ulonglong2* __restrict__ wr =
                (const ulonglong2*)(Wrs + k * WPAD + jq * 16);
            unsigned long long aAp = pack2(aAv[kk]);
            unsigned long long hAp = pack2(hAv[kk]);
            unsigned long long aBp = pack2(aBv[kk]);
            unsigned long long hBp = pack2(hBv[kk]);
#pragma unroll
            for (int j2 = 0; j2 < 4; j2++) {
                ulonglong2 L = wl[j2];
                ulonglong2 R = wr[j2];
                ffma2(accA[2 * j2 + 0], aAp, L.x);
                ffma2(accA[2 * j2 + 1], aAp, L.y);
                ffma2(accA[2 * j2 + 0], hAp, R.x);
                ffma2(accA[2 * j2 + 1], hAp, R.y);
                ffma2(accB[2 * j2 + 0], aBp, L.x);
                ffma2(accB[2 * j2 + 1], aBp, L.y);
                ffma2(accB[2 * j2 + 0], hBp, R.x);
                ffma2(accB[2 * j2 + 1], hBp, R.y);
            }
        }
    }

    float o[16];
#pragma unroll
    for (int q = 0; q < 8; q++) unpack2(accA[q], o[2 * q], o[2 * q + 1]);
    {
        const float4* res = (const float4*)&stH[p * WPAD + jq * 16];
#pragma unroll
        for (int f = 0; f < 4; f++) {
            float4 r = res[f];
            o[4 * f + 0] = fmaxf(o[4 * f + 0], 0.f) + r.x;
            o[4 * f + 1] = fmaxf(o[4 * f + 1], 0.f) + r.y;
            o[4 * f + 2] = fmaxf(o[4 * f + 2], 0.f) + r.z;
            o[4 * f + 3] = fmaxf(o[4 * f + 3], 0.f) + r.w;
        }
    }
    float o1[16];
#pragma unroll
    for (int q = 0; q < 8; q++) unpack2(accB[q], o1[2 * q], o1[2 * q + 1]);
    {
        const float4* res = (const float4*)&stH[(p + 64) * WPAD + jq * 16];
#pragma unroll
        for (int f = 0; f < 4; f++) {
            float4 r = res[f];
            o1[4 * f + 0] = fmaxf(o1[4 * f + 0], 0.f) + r.x;
            o1[4 * f + 1] = fmaxf(o1[4 * f + 1], 0.f) + r.y;
            o1[4 * f + 2] = fmaxf(o1[4 * f + 2], 0.f) + r.z;
            o1[4 * f + 3] = fmaxf(o1[4 * f + 3], 0.f) + r.w;
        }
    }
    __syncthreads();
    {
        float4* s0 = (float4*)&stA[p * WPAD + jq * 16];
        float4* s1 = (float4*)&stA[(p + 64) * WPAD + jq * 16];
#pragma unroll
        for (int f = 0; f < 4; f++) {
            s0[f] = make_float4(o[4 * f], o[4 * f + 1], o[4 * f + 2], o[4 * f + 3]);
            s1[f] = make_float4(o1[4 * f], o1[4 * f + 1], o1[4 * f + 2], o1[4 * f + 3]);
        }
    }
    __syncthreads();
    for (int i = t; i < 2048; i += 256) {
        int row = i >> 4, f = i & 15;
        int gn = base + row;
        if (gn < NN) {
            float4 vv = *(const float4*)&stA[row * WPAD + f * 4];
            *(float4*)(hout + gn * 64 + f * 4) = vv;
            if (write_hh) {
                __half2 l2 = __floats2half2_rn(vv.x, vv.y);
                __half2 h2 = __floats2half2_rn(vv.z, vv.w);
                unsigned int ul = *(unsigned int*)&l2;
                unsigned int uh = *(unsigned int*)&h2;
                ((uint2*)d_hh)[gn * 16 + f] = make_uint2(ul, uh);
            }
        }
    }
}

// ---------------- global mean pool (coalesced) + gcnt + deg re-zero -------------
__global__ void k_pool(int sel) {
    int tid = blockIdx.x * blockDim.x + threadIdx.x;
    int z = tid * 2;
    if (z < NN) {
        d_deg[z] = 0;
        if (z + 1 < NN) d_deg[z + 1] = 0;
    }

    const float* __restrict__ h = sel ? d_h1 : d_h0;
    int warp = threadIdx.x >> 5, lane = threadIdx.x & 31;
    int rbase = blockIdx.x * 512 + warp * 64;
    if (rbase >= NN) return;
    int rowoff = lane >> 4;
    int f4 = lane & 15;
    float a0 = 0.f, a1 = 0.f, a2 = 0.f, a3 = 0.f;
    int cnt = 0;
    int cur = -1;
    for (int it = 0; it < 32; it++) {
        int row = rbase + it * 2 + rowoff;
        if (row >= NN) break;
        int b = d_batch32[row];
        if (b != cur) {
            if (cur >= 0) {
                atomicAdd(&d_gsum[cur * HD + f4 * 4 + 0], a0);
                atomicAdd(&d_gsum[cur * HD + f4 * 4 + 1], a1);
                atomicAdd(&d_gsum[cur * HD + f4 * 4 + 2], a2);
                atomicAdd(&d_gsum[cur * HD + f4 * 4 + 3], a3);
                if (f4 == 0) atomicAdd(&d_gcnt[cur], cnt);
            }
            a0 = a1 = a2 = a3 = 0.f;
            cnt = 0;
            cur = b;
        }
        float4 v = *(const float4*)(h + row * HD + f4 * 4);
        a0 += v.x; a1 += v.y; a2 += v.z; a3 += v.w;
        cnt++;
    }
    if (cur >= 0) {
        atomicAdd(&d_gsum[cur * HD + f4 * 4 + 0], a0);
        atomicAdd(&d_gsum[cur * HD + f4 * 4 + 1], a1);
        atomicAdd(&d_gsum[cur * HD + f4 * 4 + 2], a2);
        atomicAdd(&d_gsum[cur * HD + f4 * 4 + 3], a3);
        if (f4 == 0) atomicAdd(&d_gcnt[cur], cnt);
    }
}

// ---------------- heads: policy (blocks 0..48) + value (last block) -------------
__global__ void __launch_bounds__(128)
k_policy(const float* __restrict__ Wp, const float* __restrict__ bp,
         const float* __restrict__ Wv, const float* __restrict__ bv,
         float* __restrict__ out) {
    __shared__ float repr[NG * HD];
    int t = threadIdx.x;
    for (int i = t; i < NG * HD; i += 128) {
        int g = i >> 6;
        repr[i] = d_gsum[i] / fmaxf((float)d_gcnt[g], 1.f);
    }
    __syncthreads();

    if (blockIdx.x == gridDim.x - 1) {   // value head
        int g = t;
        if (g >= NG) return;
        float acc = 0.f;
#pragma unroll
        for (int k = 0; k < HD; k++) acc += repr[g * HD + k] * Wv[k];
        out[NG * NA + g] = tanhf(acc + bv[0]);
        return;
    }

    int a = blockIdx.x * 128 + t;
    if (a >= NA) return;
    float acc[NG];
#pragma unroll
    for (int g = 0; g < NG; g++) acc[g] = 0.f;
    const float4* __restrict__ wr = (const float4*)(Wp + a * HD);
#pragma unroll 2
    for (int k4 = 0; k4 < 16; k4++) {
        float4 w = wr[k4];
#pragma unroll
        for (int g = 0; g < NG; g++) {
            float4 r = *(const float4*)(&repr[g * HD + k4 * 4]);
            acc[g] += w.x * r.x + w.y * r.y + w.z * r.z + w.w * r.w;
        }
    }
    float bias = bp[a];
#pragma unroll
    for (int g = 0; g < NG; g++) out[g * NA + a] = acc[g] + bias;
}

// ---------------- launcher -----------------------------------------------------
extern "C" void kernel_launch(void* const* d_in, const int* in_sizes, int n_in,
                              void* d_out, int out_size) {
    const float* x     = (const float*)d_in[0];
    const void*  edge  = d_in[1];
    const void*  batch = d_in[2];
    const float* Wenc  = (const float*)d_in[3];
    const float* benc  = (const float*)d_in[4];
    const float* Wl    = (const float*)d_in[5];
    const float* bl    = (const float*)d_in[6];
    const float* Wr    = (const float*)d_in[7];
    const float* Wp    = (const float*)d_in[8];
    const float* bp    = (const float*)d_in[9];
    const float* Wv    = (const float*)d_in[10];
    const float* bv    = (const float*)d_in[11];
    float* out = (float*)d_out;

    cudaFuncSetAttribute(k_layer, cudaFuncAttributeMaxDynamicSharedMemorySize,
                         LAYER_SMEM_BYTES);

    k_degree<<<(NE + 255) / 256, 256>>>(edge);                     // idx 0
    k_scan_a<<<98, 256>>>();                                       // idx 1
    k_scan_c<<<(NN + 255) / 256, 256>>>(batch);                    // idx 2

    // INSTRUMENTATION: dummy layer v6 at profiled stream index 3.
    // mode 2: reads h0 + d_agg16 (both from previous replay -> identical each
    // replay), writes d_scr (never read), write_hh=0. Deterministic.
    k_layer<<<(NN + 127) / 128, 256, LAYER_SMEM_BYTES>>>(2, 0, Wl, bl, Wr);  // idx 3

    k_scatter<<<(NE + 255) / 256, 256>>>(edge);                    // idx 4
    k_encoder<<<(NN * 32 + 255) / 256, 256>>>(x, Wenc, benc);      // idx 5

    for (int i = 0; i < NL; i++) {
        k_aggregate<<<(NN * 32 + 255) / 256, 256>>>();
        k_layer<<<(NN + 127) / 128, 256, LAYER_SMEM_BYTES>>>(
            i & 1, (i < NL - 1) ? 1 : 0,
            Wl + i * HD * HD, bl + i * HD, Wr + i * HD * HD);
    }

    k_pool<<<(NN + 511) / 512, 256>>>(0);   // final h is d_h0 after 4 layers
    k_policy<<<(NA + 127) / 128 + 1, 128>>>(Wp, bp, Wv, bv, out);
}

// round 16
// speedup vs baseline: 1.0864x; 1.0864x over previous
#include <cuda_runtime.h>
#include <cuda_fp16.h>
#include <math.h>

#define NN 100000
#define NE 3200000
#define FIN 32
#define HD 64
#define NL 4
#define NA 6158
#define NG 64
#define WPAD 68

// dynamic smem layout for k_layer v7 (floats):
//  Wsm [0,4352) | bls [4352,4416) | stage [4416,13120)
#define OFF_W 0
#define OFF_B 4352
#define OFF_ST 4416
#define LAYER_SMEM_FLOATS 13120
#define LAYER_SMEM_BYTES (LAYER_SMEM_FLOATS * 4)

// ---------------- scratch (device globals; no allocation allowed) -------------
__device__ int   d_flag;
__device__ int   d_batch32[NN];
__device__ int   d_deg[NN];
__device__ int   d_rowptr[NN + 1];
__device__ int   d_cursor[NN];
__device__ int   d_csr[NE];
__device__ float d_invdeg[NN];
__device__ float d_h0[NN * HD];
__device__ float d_h1[NN * HD];
__device__ __half2 d_hh[NN * 32];
__device__ __half2 d_agg16[NN * 32];
__device__ float d_gsum[NG * HD];
__device__ int   d_gcnt[NG];
__device__ int   d_part[256];

// ---------------- f32x2 packed-FMA helpers -------------------------------------
__device__ __forceinline__ unsigned long long pack2(float x) {
    unsigned long long r;
    asm("mov.b64 %0, {%1, %1};" : "=l"(r) : "f"(x));
    return r;
}
__device__ __forceinline__ void ffma2(unsigned long long& d,
                                      unsigned long long a,
                                      unsigned long long b) {
    asm("fma.rn.f32x2 %0, %1, %2, %0;" : "+l"(d) : "l"(a), "l"(b));
}
__device__ __forceinline__ void unpack2(unsigned long long v, float& lo, float& hi) {
    asm("mov.b64 {%0, %1}, %2;" : "=f"(lo), "=f"(hi) : "l"(v));
}

// ---------------- degree count straight from edge dst half ----------------------
__global__ void k_degree(const void* edge) {
    __shared__ int sflag;
    if (threadIdx.x < 32) {
        const unsigned int* w = (const unsigned int*)edge;
        unsigned int m0 = __ballot_sync(0xffffffffu, w[2 * threadIdx.x + 1] == 0u);
        unsigned int m1 = __ballot_sync(0xffffffffu, w[2 * (threadIdx.x + 32) + 1] == 0u);
        if (threadIdx.x == 0) {
            int f = (__popc(m0) + __popc(m1) >= 60) ? 1 : 0;
            sflag = f;
            if (blockIdx.x == 0) d_flag = f;
        }
    }
    __syncthreads();
    int e = blockIdx.x * blockDim.x + threadIdx.x;
    if (e >= NE) return;
    int dd;
    if (sflag) dd = (int)((const long long*)edge)[NE + e];
    else       dd = ((const int*)edge)[NE + e];
    atomicAdd(&d_deg[dd], 1);
}

// ---------------- CSR build (scan over degrees) --------------------------------
__global__ void k_scan_a() {
    __shared__ int ts[256];
    int b = blockIdx.x, t = threadIdx.x;
    int base = b * 1024 + t * 4;
    int v[4];
    int s = 0;
#pragma unroll
    for (int j = 0; j < 4; j++) {
        int idx = base + j;
        v[j] = (idx < NN) ? d_deg[idx] : 0;
        s += v[j];
    }
    ts[t] = s;
    __syncthreads();
    for (int off = 1; off < 256; off <<= 1) {
        int x = (t >= off) ? ts[t - off] : 0;
        __syncthreads();
        ts[t] += x;
        __syncthreads();
    }
    int run = ts[t] - s;
#pragma unroll
    for (int j = 0; j < 4; j++) {
        int idx = base + j;
        if (idx < NN) d_rowptr[idx] = run;
        run += v[j];
    }
    if (t == 255) d_part[b] = ts[255];
}

// scan finalize + invdeg + batch conversion
__global__ void k_scan_c(const void* batch) {
    __shared__ int ps[128];
    int t = threadIdx.x;
    int orig = (t < 98) ? d_part[t] : 0;
    if (t < 128) ps[t] = orig;
    __syncthreads();
    for (int off = 1; off < 128; off <<= 1) {
        int x = (t >= off && t < 128) ? ps[t - off] : 0;
        __syncthreads();
        if (t < 128) ps[t] += x;
        __syncthreads();
    }
    if (t < 128) ps[t] -= orig;   // exclusive
    __syncthreads();

    int i = blockIdx.x * blockDim.x + t;
    if (i == 0) d_rowptr[NN] = NE;
    if (i >= NN) return;
    int r = d_rowptr[i] + ps[i >> 10];
    d_rowptr[i] = r;
    d_cursor[i] = r;
    d_invdeg[i] = 1.0f / fmaxf((float)d_deg[i], 1.0f);
    int b;
    if (d_flag) b = (int)((const long long*)batch)[i];
    else        b = ((const int*)batch)[i];
    d_batch32[i] = b;
}

// scatter edges into CSR, converting src/dst inline; zeroes gsum/gcnt
__global__ void k_scatter(const void* edge) {
    int e = blockIdx.x * blockDim.x + threadIdx.x;
    if (e < NG * HD) d_gsum[e] = 0.f;
    if (e < NG) d_gcnt[e] = 0;
    if (e >= NE) return;
    int ss, dd;
    if (d_flag) {
        ss = (int)((const long long*)edge)[e];
        dd = (int)((const long long*)edge)[NE + e];
    } else {
        ss = ((const int*)edge)[e];
        dd = ((const int*)edge)[NE + e];
    }
    int pos = atomicAdd(&d_cursor[dd], 1);
    d_csr[pos] = ss;
}

// ---------------- encoder: h0 = relu(x @ W_enc^T + b_enc) ----------------------
__global__ void k_encoder(const float* __restrict__ x,
                          const float* __restrict__ Wenc,
                          const float* __restrict__ benc) {
    __shared__ float Ws[FIN * HD];
    __shared__ float bs[HD];
    int t = threadIdx.x;
    int gid = blockIdx.x * blockDim.x + t;
    for (int i = t; i < HD * FIN; i += blockDim.x) {
        int j = i / FIN, k = i % FIN;
        Ws[k * HD + j] = Wenc[i];
    }
    if (t < HD) bs[t] = benc[t];
    __syncthreads();
    if (gid >= NN * 32) return;
    int n = gid >> 5, j2 = gid & 31;
    int j = 2 * j2;
    const float* xr = x + n * FIN;
    float a0 = bs[j], a1 = bs[j + 1];
#pragma unroll
    for (int k = 0; k < FIN; k += 4) {
        float4 xv = *(const float4*)(xr + k);
        float2 w0 = *(const float2*)(&Ws[k * HD + j]);
        float2 w1 = *(const float2*)(&Ws[(k + 1) * HD + j]);
        float2 w2 = *(const float2*)(&Ws[(k + 2) * HD + j]);
        float2 w3 = *(const float2*)(&Ws[(k + 3) * HD + j]);
        a0 += xv.x * w0.x + xv.y * w1.x + xv.z * w2.x + xv.w * w3.x;
        a1 += xv.x * w0.y + xv.y * w1.y + xv.z * w2.y + xv.w * w3.y;
    }
    a0 = fmaxf(a0, 0.f);
    a1 = fmaxf(a1, 0.f);
    ((float2*)d_h0)[gid] = make_float2(a0, a1);
    d_hh[gid] = __floats2half2_rn(a0, a1);
}

// ---------------- aggregation -> fp16 -------------------------------------------
__global__ void k_aggregate() {
    int w = (blockIdx.x * blockDim.x + threadIdx.x) >> 5;
    if (w >= NN) return;
    int lane = threadIdx.x & 31;
    int beg = d_rowptr[w], end = d_rowptr[w + 1];
    const __half2* __restrict__ hp = d_hh;
    float ax0 = 0.f, ay0 = 0.f, ax1 = 0.f, ay1 = 0.f;
    int i = beg;
    for (; i + 8 <= end; i += 8) {
        int s0 = d_csr[i + 0], s1 = d_csr[i + 1], s2 = d_csr[i + 2], s3 = d_csr[i + 3];
        int s4 = d_csr[i + 4], s5 = d_csr[i + 5], s6 = d_csr[i + 6], s7 = d_csr[i + 7];
        float2 v0 = __half22float2(hp[s0 * 32 + lane]);
        float2 v1 = __half22float2(hp[s1 * 32 + lane]);
        float2 v2 = __half22float2(hp[s2 * 32 + lane]);
        float2 v3 = __half22float2(hp[s3 * 32 + lane]);
        float2 v4 = __half22float2(hp[s4 * 32 + lane]);
        float2 v5 = __half22float2(hp[s5 * 32 + lane]);
        float2 v6 = __half22float2(hp[s6 * 32 + lane]);
        float2 v7 = __half22float2(hp[s7 * 32 + lane]);
        ax0 += v0.x + v1.x + v2.x + v3.x;
        ay0 += v0.y + v1.y + v2.y + v3.y;
        ax1 += v4.x + v5.x + v6.x + v7.x;
        ay1 += v4.y + v5.y + v6.y + v7.y;
    }
    for (; i < end; i++) {
        float2 v = __half22float2(hp[d_csr[i] * 32 + lane]);
        ax0 += v.x; ay0 += v.y;
    }
    float id = d_invdeg[w];
    d_agg16[w * 32 + lane] = __floats2half2_rn((ax0 + ax1) * id, (ay0 + ay1) * id);
}

// ---------------- layer v7: phased single-W single-stage, 4 blocks/SM -----------
// 128 nodes/block; thread = (p = t&63 -> nodes p, p+64; jq = t>>6 -> j quarter).
// Phase 1: Wsm=Wl, stage=agg (fp16->fp32). Phase 2: Wsm=Wr, stage=h (fp32),
// residual from stage. smem 52.5KB -> occupancy 4 blocks (32 warps/SM).
__global__ void __launch_bounds__(256, 4)
k_layer(int mode, int write_hh,
        const float* __restrict__ Wl, const float* __restrict__ bl,
        const float* __restrict__ Wr) {
    const float* h    = (mode == 1) ? d_h1 : d_h0;
    float*       hout = (mode == 0) ? d_h1 : d_h0;
    extern __shared__ float S[];
    float* Wsm   = S + OFF_W;
    float* bls   = S + OFF_B;
    float* stage = S + OFF_ST;
    int t = threadIdx.x;
    int base = blockIdx.x * 128;
    int p  = t & 63;
    int jq = t >> 6;

    // ---- phase 1 setup: Wl + agg ----
    for (int i = t; i < HD * HD; i += 256) {
        int j = i >> 6, k = i & 63;
        Wsm[k * WPAD + j] = Wl[i];
    }
    if (t < HD) bls[t] = bl[t];
    for (int i = t; i < 1024; i += 256) {       // 128 rows x 8 uint4 of fp16
        int row = i >> 3, f = i & 7;
        int gn = base + row;
        if (gn < NN) {
            uint4 q = ((const uint4*)(d_agg16 + gn * 32))[f];
            const __half2* hq = (const __half2*)&q;
            float2 f0 = __half22float2(hq[0]);
            float2 f1 = __half22float2(hq[1]);
            float2 f2 = __half22float2(hq[2]);
            float2 f3 = __half22float2(hq[3]);
            float* dst = &stage[row * WPAD + f * 8];
            *(float4*)(dst)     = make_float4(f0.x, f0.y, f1.x, f1.y);
            *(float4*)(dst + 4) = make_float4(f2.x, f2.y, f3.x, f3.y);
        }
    }
    __syncthreads();

    unsigned long long accA[8], accB[8];
    {
        const unsigned long long* bp2 = (const unsigned long long*)(bls + jq * 16);
#pragma unroll
        for (int q = 0; q < 8; q++) { accA[q] = bp2[q]; accB[q] = bp2[q]; }
    }

    // ---- phase 1 GEMM: acc += agg @ Wl^T ----
#pragma unroll 2
    for (int k4 = 0; k4 < 16; k4++) {
        float4 aA = *(const float4*)&stage[p * WPAD + k4 * 4];
        float4 aB = *(const float4*)&stage[(p + 64) * WPAD + k4 * 4];
        float aAv[4] = {aA.x, aA.y, aA.z, aA.w};
        float aBv[4] = {aB.x, aB.y, aB.z, aB.w};
#pragma unroll
        for (int kk = 0; kk < 4; kk++) {
            int k = k4 * 4 + kk;
            const ulonglong2* __restrict__ wv =
                (const ulonglong2*)(Wsm + k * WPAD + jq * 16);
            unsigned long long ap = pack2(aAv[kk]);
            unsigned long long bp = pack2(aBv[kk]);
#pragma unroll
            for (int j2 = 0; j2 < 4; j2++) {
                ulonglong2 L = wv[j2];
                ffma2(accA[2 * j2 + 0], ap, L.x);
                ffma2(accA[2 * j2 + 1], ap, L.y);
                ffma2(accB[2 * j2 + 0], bp, L.x);
                ffma2(accB[2 * j2 + 1], bp, L.y);
            }
        }
    }
    __syncthreads();   // phase-1 reads done

    // ---- phase 2 setup: Wr + h ----
    for (int i = t; i < HD * HD; i += 256) {
        int j = i >> 6, k = i & 63;
        Wsm[k * WPAD + j] = Wr[i];
    }
    for (int i = t; i < 2048; i += 256) {
        int row = i >> 4, f = i & 15;
        int gn = base + row;
        if (gn < NN)
            *(float4*)&stage[row * WPAD + f * 4] = ((const float4*)(h + gn * 64))[f];
    }
    __syncthreads();

    // ---- phase 2 GEMM: acc += h @ Wr^T ----
#pragma unroll 2
    for (int k4 = 0; k4 < 16; k4++) {
        float4 hA = *(const float4*)&stage[p * WPAD + k4 * 4];
        float4 hB = *(const float4*)&stage[(p + 64) * WPAD + k4 * 4];
        float hAv[4] = {hA.x, hA.y, hA.z, hA.w};
        float hBv[4] = {hB.x, hB.y, hB.z, hB.w};
#pragma unroll
        for (int kk = 0; kk < 4; kk++) {
            int k = k4 * 4 + kk;
            const ulonglong2* __restrict__ wv =
                (const ulonglong2*)(Wsm + k * WPAD + jq * 16);
            unsigned long long ap = pack2(hAv[kk]);
            unsigned long long bp = pack2(hBv[kk]);
#pragma unroll
            for (int j2 = 0; j2 < 4; j2++) {
                ulonglong2 R = wv[j2];
                ffma2(accA[2 * j2 + 0], ap, R.x);
                ffma2(accA[2 * j2 + 1], ap, R.y);
                ffma2(accB[2 * j2 + 0], bp, R.x);
                ffma2(accB[2 * j2 + 1], bp, R.y);
            }
        }
    }

    // ---- epilogue: relu + residual (stage holds h), then restage outputs ----
    float o[16], o1[16];
#pragma unroll
    for (int q = 0; q < 8; q++) unpack2(accA[q], o[2 * q], o[2 * q + 1]);
    {
        const float4* res = (const float4*)&stage[p * WPAD + jq * 16];
#pragma unroll
        for (int f = 0; f < 4; f++) {
            float4 r = res[f];
            o[4 * f + 0] = fmaxf(o[4 * f + 0], 0.f) + r.x;
            o[4 * f + 1] = fmaxf(o[4 * f + 1], 0.f) + r.y;
            o[4 * f + 2] = fmaxf(o[4 * f + 2], 0.f) + r.z;
            o[4 * f + 3] = fmaxf(o[4 * f + 3], 0.f) + r.w;
        }
    }
#pragma unroll
    for (int q = 0; q < 8; q++) unpack2(accB[q], o1[2 * q], o1[2 * q + 1]);
    {
        const float4* res = (const float4*)&stage[(p + 64) * WPAD + jq * 16];
#pragma unroll
        for (int f = 0; f < 4; f++) {
            float4 r = res[f];
            o1[4 * f + 0] = fmaxf(o1[4 * f + 0], 0.f) + r.x;
            o1[4 * f + 1] = fmaxf(o1[4 * f + 1], 0.f) + r.y;
            o1[4 * f + 2] = fmaxf(o1[4 * f + 2], 0.f) + r.z;
            o1[4 * f + 3] = fmaxf(o1[4 * f + 3], 0.f) + r.w;
        }
    }
    __syncthreads();   // all phase-2/residual stage reads done
    {
        float4* s0 = (float4*)&stage[p * WPAD + jq * 16];
        float4* s1 = (float4*)&stage[(p + 64) * WPAD + jq * 16];
#pragma unroll
        for (int f = 0; f < 4; f++) {
            s0[f] = make_float4(o[4 * f], o[4 * f + 1], o[4 * f + 2], o[4 * f + 3]);
            s1[f] = make_float4(o1[4 * f], o1[4 * f + 1], o1[4 * f + 2], o1[4 * f + 3]);
        }
    }
    __syncthreads();
    for (int i = t; i < 2048; i += 256) {
        int row = i >> 4, f = i & 15;
        int gn = base + row;
        if (gn < NN) {
            float4 vv = *(const float4*)&stage[row * WPAD + f * 4];
            *(float4*)(hout + gn * 64 + f * 4) = vv;
            if (write_hh) {
                __half2 l2 = __floats2half2_rn(vv.x, vv.y);
                __half2 h2 = __floats2half2_rn(vv.z, vv.w);
                unsigned int ul = *(unsigned int*)&l2;
                unsigned int uh = *(unsigned int*)&h2;
                ((uint2*)d_hh)[gn * 16 + f] = make_uint2(ul, uh);
            }
        }
    }
}

// ---------------- global mean pool (coalesced) + gcnt + deg re-zero -------------
__global__ void k_pool(int sel) {
    int tid = blockIdx.x * blockDim.x + threadIdx.x;
    int z = tid * 2;
    if (z < NN) {
        d_deg[z] = 0;
        if (z + 1 < NN) d_deg[z + 1] = 0;
    }

    const float* __restrict__ h = sel ? d_h1 : d_h0;
    int warp = threadIdx.x >> 5, lane = threadIdx.x & 31;
    int rbase = blockIdx.x * 512 + warp * 64;
    if (rbase >= NN) return;
    int rowoff = lane >> 4;
    int f4 = lane & 15;
    float a0 = 0.f, a1 = 0.f, a2 = 0.f, a3 = 0.f;
    int cnt = 0;
    int cur = -1;
    for (int it = 0; it < 32; it++) {
        int row = rbase + it * 2 + rowoff;
        if (row >= NN) break;
        int b = d_batch32[row];
        if (b != cur) {
            if (cur >= 0) {
                atomicAdd(&d_gsum[cur * HD + f4 * 4 + 0], a0);
                atomicAdd(&d_gsum[cur * HD + f4 * 4 + 1], a1);
                atomicAdd(&d_gsum[cur * HD + f4 * 4 + 2], a2);
                atomicAdd(&d_gsum[cur * HD + f4 * 4 + 3], a3);
                if (f4 == 0) atomicAdd(&d_gcnt[cur], cnt);
            }
            a0 = a1 = a2 = a3 = 0.f;
            cnt = 0;
            cur = b;
        }
        float4 v = *(const float4*)(h + row * HD + f4 * 4);
        a0 += v.x; a1 += v.y; a2 += v.z; a3 += v.w;
        cnt++;
    }
    if (cur >= 0) {
        atomicAdd(&d_gsum[cur * HD + f4 * 4 + 0], a0);
        atomicAdd(&d_gsum[cur * HD + f4 * 4 + 1], a1);
        atomicAdd(&d_gsum[cur * HD + f4 * 4 + 2], a2);
        atomicAdd(&d_gsum[cur * HD + f4 * 4 + 3], a3);
        if (f4 == 0) atomicAdd(&d_gcnt[cur], cnt);
    }
}

// ---------------- heads: policy (blocks 0..48) + value (last block) -------------
__global__ void __launch_bounds__(128)
k_policy(const float* __restrict__ Wp, const float* __restrict__ bp,
         const float* __restrict__ Wv, const float* __restrict__ bv,
         float* __restrict__ out) {
    __shared__ float repr[NG * HD];
    int t = threadIdx.x;
    for (int i = t; i < NG * HD; i += 128) {
        int g = i >> 6;
        repr[i] = d_gsum[i] / fmaxf((float)d_gcnt[g], 1.f);
    }
    __syncthreads();

    if (blockIdx.x == gridDim.x - 1) {   // value head
        int g = t;
        if (g >= NG) return;
        float acc = 0.f;
#pragma unroll
        for (int k = 0; k < HD; k++) acc += repr[g * HD + k] * Wv[k];
        out[NG * NA + g] = tanhf(acc + bv[0]);
        return;
    }

    int a = blockIdx.x * 128 + t;
    if (a >= NA) return;
    float acc[NG];
#pragma unroll
    for (int g = 0; g < NG; g++) acc[g] = 0.f;
    const float4* __restrict__ wr = (const float4*)(Wp + a * HD);
#pragma unroll 2
    for (int k4 = 0; k4 < 16; k4++) {
        float4 w = wr[k4];
#pragma unroll
        for (int g = 0; g < NG; g++) {
            float4 r = *(const float4*)(&repr[g * HD + k4 * 4]);
            acc[g] += w.x * r.x + w.y * r.y + w.z * r.z + w.w * r.w;
        }
    }
    float bias = bp[a];
#pragma unroll
    for (int g = 0; g < NG; g++) out[g * NA + a] = acc[g] + bias;
}

// ---------------- launcher -----------------------------------------------------
extern "C" void kernel_launch(void* const* d_in, const int* in_sizes, int n_in,
                              void* d_out, int out_size) {
    const float* x     = (const float*)d_in[0];
    const void*  edge  = d_in[1];
    const void*  batch = d_in[2];
    const float* Wenc  = (const float*)d_in[3];
    const float* benc  = (const float*)d_in[4];
    const float* Wl    = (const float*)d_in[5];
    const float* bl    = (const float*)d_in[6];
    const float* Wr    = (const float*)d_in[7];
    const float* Wp    = (const float*)d_in[8];
    const float* bp    = (const float*)d_in[9];
    const float* Wv    = (const float*)d_in[10];
    const float* bv    = (const float*)d_in[11];
    float* out = (float*)d_out;

    cudaFuncSetAttribute(k_layer, cudaFuncAttributeMaxDynamicSharedMemorySize,
                         LAYER_SMEM_BYTES);

    k_degree<<<(NE + 255) / 256, 256>>>(edge);                     // idx 0
    k_scan_a<<<98, 256>>>();                                       // idx 1
    k_scan_c<<<(NN + 255) / 256, 256>>>(batch);                    // idx 2
    k_scatter<<<(NE + 255) / 256, 256>>>(edge);                    // idx 3 (profiled)
    k_encoder<<<(NN * 32 + 255) / 256, 256>>>(x, Wenc, benc);      // idx 4

    for (int i = 0; i < NL; i++) {
        k_aggregate<<<(NN * 32 + 255) / 256, 256>>>();
        k_layer<<<(NN + 127) / 128, 256, LAYER_SMEM_BYTES>>>(
            i & 1, (i < NL - 1) ? 1 : 0,
            Wl + i * HD * HD, bl + i * HD, Wr + i * HD * HD);
    }

    k_pool<<<(NN + 511) / 512, 256>>>(0);   // final h is d_h0 after 4 layers
    k_policy<<<(NA + 127) / 128 + 1, 128>>>(Wp, bp, Wv, bv, out);
}